// round 1
// baseline (speedup 1.0000x reference)
#include <cuda_runtime.h>
#include <cstdint>

// Problem constants
#define Bz   4
#define Az   3
#define Sz   1024
#define Hz   768
#define NHz  12
#define HDz  64

// -------------------- scratch (device globals; no allocation) --------------------
__device__ float g_Q  [Bz*NHz*Sz*HDz];        // [b][h][s][d], pre-scaled by 1/8
__device__ float g_K  [Bz*NHz*Az*Sz*HDz];     // [b][h][a][s][d]
__device__ float g_V  [Bz*NHz*Az*Sz*HDz];     // [b][h][a][s][d]
__device__ float g_att[Bz*Sz*Hz];             // attended, [b][s][h*64+d]
__device__ float g_res[Bz*Sz*Hz];             // attended@Wo^T + bo + query (pre-LN)

// -------------------- packed f32x2 helpers --------------------
typedef unsigned long long u64;

__device__ __forceinline__ u64 pk2(float lo, float hi) {
    u64 r; asm("mov.b64 %0, {%1,%2};" : "=l"(r) : "f"(lo), "f"(hi)); return r;
}
__device__ __forceinline__ void upk2(u64 v, float& lo, float& hi) {
    asm("mov.b64 {%0,%1}, %2;" : "=f"(lo), "=f"(hi) : "l"(v));
}
__device__ __forceinline__ void fma2(u64& d, u64 a, u64 b) {
    asm("fma.rn.f32x2 %0, %1, %2, %0;" : "+l"(d) : "l"(a), "l"(b));
}

// -------------------- fast exp2 / rcp (keep MUFU out of the hot loop) --------------------
__device__ __forceinline__ float fexp2(float x) {
    // x in (-120, 0]; degree-6 Taylor of 2^f on [0,1), max rel err ~1.5e-5
    x = fmaxf(x, -120.0f);
    float n = floorf(x);
    float f = x - n;
    float p =             1.5404e-4f;
    p = fmaf(p, f, 1.3333558e-3f);
    p = fmaf(p, f, 9.6181291e-3f);
    p = fmaf(p, f, 5.5504109e-2f);
    p = fmaf(p, f, 2.4022651e-1f);
    p = fmaf(p, f, 6.9314718e-1f);
    p = fmaf(p, f, 1.0f);
    int e = (int)n;                       // exact (n integral, in [-120,0])
    float sc = __int_as_float((e + 127) << 23);
    return p * sc;
}
__device__ __forceinline__ float frcp(float s) {
    // bit-trick seed + 3 Newton iterations; s in [1,3]
    float x = __int_as_float(0x7EF311C3u - __float_as_int(s));
    x = x * fmaf(-s, x, 2.0f);
    x = x * fmaf(-s, x, 2.0f);
    x = x * fmaf(-s, x, 2.0f);
    return x;
}
__device__ __forceinline__ void softmax3(float& a, float& b, float& c) {
    const float L2E = 1.4426950408889634f;
    float m  = fmaxf(a, fmaxf(b, c));
    float mL = m * L2E;
    float e0 = fexp2(fmaf(a, L2E, -mL));
    float e1 = fexp2(fmaf(b, L2E, -mL));
    float e2 = fexp2(fmaf(c, L2E, -mL));
    float r  = frcp(e0 + e1 + e2);
    a = e0 * r; b = e1 * r; c = e2 * r;
}

// -------------------- projection GEMM: out = X[M,768] @ W[N=768,K=768]^T + b --------------------
// MODE 0: X=query   -> g_Q   (scaled by 1/8, head layout)
// MODE 1: X=adapter -> g_K   (head layout)
// MODE 2: X=adapter -> g_V   (head layout)
// MODE 3: X=g_att   -> g_res (+ bias + residual(query))
template <int MODE>
__global__ void __launch_bounds__(256)
gemm_proj(const float* __restrict__ X, const float* __restrict__ W,
          const float* __restrict__ bias, const float* __restrict__ resid)
{
    __shared__ __align__(16) float Xs[16][68];
    __shared__ __align__(16) float Ws[16][68];

    const int tid = threadIdx.x;
    const int tx  = tid & 15, ty = tid >> 4;
    const int m0  = blockIdx.y * 64, n0 = blockIdx.x * 64;
    const int lrow = tid >> 2, lk = (tid & 3) * 4;

    const float* Xsrc = (MODE == 3) ? (const float*)g_att : X;
    float* dst = (MODE == 0) ? g_Q : (MODE == 1) ? g_K : (MODE == 2) ? g_V : g_res;

    const float* Xp = Xsrc + (size_t)(m0 + lrow) * Hz + lk;
    const float* Wp = W    + (size_t)(n0 + lrow) * Hz + lk;

    u64 acc[4][2];
#pragma unroll
    for (int i = 0; i < 4; i++) { acc[i][0] = 0ULL; acc[i][1] = 0ULL; }

    for (int kt = 0; kt < Hz; kt += 16) {
        float4 xv = *(const float4*)(Xp + kt);
        float4 wv = *(const float4*)(Wp + kt);
        __syncthreads();
        Xs[lk+0][lrow] = xv.x; Xs[lk+1][lrow] = xv.y; Xs[lk+2][lrow] = xv.z; Xs[lk+3][lrow] = xv.w;
        Ws[lk+0][lrow] = wv.x; Ws[lk+1][lrow] = wv.y; Ws[lk+2][lrow] = wv.z; Ws[lk+3][lrow] = wv.w;
        __syncthreads();
#pragma unroll
        for (int kk = 0; kk < 16; kk++) {
            float4      a4 = *(const float4*)    &Xs[kk][ty * 4];
            ulonglong2  b2 = *(const ulonglong2*)&Ws[kk][tx * 4];
            u64 d0 = pk2(a4.x, a4.x), d1 = pk2(a4.y, a4.y);
            u64 d2 = pk2(a4.z, a4.z), d3 = pk2(a4.w, a4.w);
            fma2(acc[0][0], d0, b2.x); fma2(acc[0][1], d0, b2.y);
            fma2(acc[1][0], d1, b2.x); fma2(acc[1][1], d1, b2.y);
            fma2(acc[2][0], d2, b2.x); fma2(acc[2][1], d2, b2.y);
            fma2(acc[3][0], d3, b2.x); fma2(acc[3][1], d3, b2.y);
        }
    }

#pragma unroll
    for (int i = 0; i < 4; i++) {
        const int m = m0 + ty * 4 + i;
        float v[4];
        upk2(acc[i][0], v[0], v[1]);
        upk2(acc[i][1], v[2], v[3]);
#pragma unroll
        for (int j = 0; j < 4; j++) {
            const int n = n0 + tx * 4 + j;
            float val = v[j] + bias[n];
            if (MODE == 0) {
                int b = m / Sz, s = m % Sz, h = n >> 6, d = n & 63;
                dst[(((size_t)(b * NHz + h)) * Sz + s) * HDz + d] = val * 0.125f;
            } else if (MODE == 1 || MODE == 2) {
                int b = m / (Az * Sz), r = m % (Az * Sz);
                int a = r / Sz, s = r % Sz, h = n >> 6, d = n & 63;
                dst[((((size_t)(b * NHz + h)) * Az + a) * Sz + s) * HDz + d] = val;
            } else {
                dst[(size_t)m * Hz + n] = val + resid[(size_t)m * Hz + n];
            }
        }
    }
}

// -------------------- fused attention: per (b, h, 64-row q tile) --------------------
// smem plan (dynamic, 87040 B):
//   Qs [64 d][68]  (q cols)    -- resident
//   Ks [64][68]                -- [d][s] for K phase, [s][d] for V phase
//   Ps [3][64 q][68 s]         -- raw scores, then probabilities
__global__ void __launch_bounds__(256)
attn_kernel()
{
    extern __shared__ float smem[];
    float (*Qs)[68]     = (float(*)[68])     (smem);
    float (*Ks)[68]     = (float(*)[68])     (smem + 4352);
    float (*Ps)[64][68] = (float(*)[64][68]) (smem + 8704);

    const int tid = threadIdx.x;
    const int tx  = tid & 15, ty = tid >> 4;
    const int b   = blockIdx.z, h = blockIdx.y, q0 = blockIdx.x * 64;

    const float* Qg = g_Q + ((size_t)(b * NHz + h)) * Sz * HDz;
    const float* Kg = g_K + ((size_t)(b * NHz + h)) * Az * Sz * HDz;
    const float* Vg = g_V + ((size_t)(b * NHz + h)) * Az * Sz * HDz;

    const int row = tid >> 2;

    // load Q tile transposed: Qs[d][q]
#pragma unroll
    for (int r = 0; r < 4; r++) {
        int dq = ((tid & 3) + 4 * r) * 4;
        float4 v = *(const float4*)(Qg + (size_t)(q0 + row) * HDz + dq);
        Qs[dq+0][row] = v.x; Qs[dq+1][row] = v.y; Qs[dq+2][row] = v.z; Qs[dq+3][row] = v.w;
    }

    u64 att[4][2];
#pragma unroll
    for (int i = 0; i < 4; i++) { att[i][0] = 0ULL; att[i][1] = 0ULL; }

    __syncthreads();

    for (int s0 = 0; s0 < Sz; s0 += 64) {
        // ---- scores: for each adapter, sc = Qs @ Ks^T -> raw into Ps[a] ----
        for (int a = 0; a < 3; a++) {
            float4 kv[4];
#pragma unroll
            for (int r = 0; r < 4; r++) {
                int dq = ((tid & 3) + 4 * r) * 4;
                kv[r] = *(const float4*)(Kg + ((size_t)a * Sz + s0 + row) * HDz + dq);
            }
            __syncthreads();   // previous users of Ks done
#pragma unroll
            for (int r = 0; r < 4; r++) {
                int dq = ((tid & 3) + 4 * r) * 4;
                Ks[dq+0][row] = kv[r].x; Ks[dq+1][row] = kv[r].y;
                Ks[dq+2][row] = kv[r].z; Ks[dq+3][row] = kv[r].w;
            }
            __syncthreads();

            u64 sc[4][2];
#pragma unroll
            for (int i = 0; i < 4; i++) { sc[i][0] = 0ULL; sc[i][1] = 0ULL; }
#pragma unroll 16
            for (int kk = 0; kk < 64; kk++) {
                float4     q4 = *(const float4*)    &Qs[kk][ty * 4];
                ulonglong2 k2 = *(const ulonglong2*)&Ks[kk][tx * 4];
                u64 d0 = pk2(q4.x, q4.x), d1 = pk2(q4.y, q4.y);
                u64 d2 = pk2(q4.z, q4.z), d3 = pk2(q4.w, q4.w);
                fma2(sc[0][0], d0, k2.x); fma2(sc[0][1], d0, k2.y);
                fma2(sc[1][0], d1, k2.x); fma2(sc[1][1], d1, k2.y);
                fma2(sc[2][0], d2, k2.x); fma2(sc[2][1], d2, k2.y);
                fma2(sc[3][0], d3, k2.x); fma2(sc[3][1], d3, k2.y);
            }
#pragma unroll
            for (int i = 0; i < 4; i++) {
                float w0, w1, w2, w3;
                upk2(sc[i][0], w0, w1); upk2(sc[i][1], w2, w3);
                *(float4*)&Ps[a][ty * 4 + i][tx * 4] = make_float4(w0, w1, w2, w3);
            }
        }

        // ---- 3-way softmax over adapter axis (each thread on its own elements) ----
#pragma unroll
        for (int i = 0; i < 4; i++) {
            int q = ty * 4 + i, c = tx * 4;
            float4 A  = *(float4*)&Ps[0][q][c];
            float4 Bv = *(float4*)&Ps[1][q][c];
            float4 C  = *(float4*)&Ps[2][q][c];
            softmax3(A.x, Bv.x, C.x);
            softmax3(A.y, Bv.y, C.y);
            softmax3(A.z, Bv.z, C.z);
            softmax3(A.w, Bv.w, C.w);
            *(float4*)&Ps[0][q][c] = A;
            *(float4*)&Ps[1][q][c] = Bv;
            *(float4*)&Ps[2][q][c] = C;
        }
        __syncthreads();

        // ---- PV: att += Ps[a] @ V_a ----
        for (int a = 0; a < 3; a++) {
            float4 vv[4];
#pragma unroll
            for (int r = 0; r < 4; r++) {
                int dq = ((tid & 3) + 4 * r) * 4;
                vv[r] = *(const float4*)(Vg + ((size_t)a * Sz + s0 + row) * HDz + dq);
            }
            __syncthreads();   // previous PV compute done
#pragma unroll
            for (int r = 0; r < 4; r++) {
                int dq = ((tid & 3) + 4 * r) * 4;
                *(float4*)&Ks[row][dq] = vv[r];   // direct [s][d]
            }
            __syncthreads();
#pragma unroll 16
            for (int kk = 0; kk < 64; kk++) {
                ulonglong2 v2 = *(const ulonglong2*)&Ks[kk][tx * 4];
                float p0 = Ps[a][ty * 4 + 0][kk];
                float p1 = Ps[a][ty * 4 + 1][kk];
                float p2 = Ps[a][ty * 4 + 2][kk];
                float p3 = Ps[a][ty * 4 + 3][kk];
                u64 d0 = pk2(p0, p0), d1 = pk2(p1, p1);
                u64 d2 = pk2(p2, p2), d3 = pk2(p3, p3);
                fma2(att[0][0], d0, v2.x); fma2(att[0][1], d0, v2.y);
                fma2(att[1][0], d1, v2.x); fma2(att[1][1], d1, v2.y);
                fma2(att[2][0], d2, v2.x); fma2(att[2][1], d2, v2.y);
                fma2(att[3][0], d3, v2.x); fma2(att[3][1], d3, v2.y);
            }
        }
        __syncthreads();   // Ps safe to overwrite next tile
    }

    // write attended in [B,S,H] layout
#pragma unroll
    for (int i = 0; i < 4; i++) {
        float w0, w1, w2, w3;
        upk2(att[i][0], w0, w1); upk2(att[i][1], w2, w3);
        *(float4*)(g_att + ((size_t)b * Sz + q0 + ty * 4 + i) * Hz + h * 64 + tx * 4)
            = make_float4(w0, w1, w2, w3);
    }
}

// -------------------- LayerNorm over H=768 per row --------------------
__global__ void __launch_bounds__(256)
ln_kernel(const float* __restrict__ gamma, const float* __restrict__ beta,
          float* __restrict__ out)
{
    const int row = blockIdx.x;
    const int tid = threadIdx.x;
    const float* x = g_res + (size_t)row * Hz;

    float v0 = x[tid], v1 = x[tid + 256], v2 = x[tid + 512];
    float s  = v0 + v1 + v2;
    float ss = v0 * v0 + v1 * v1 + v2 * v2;

    __shared__ float rs[8], rss[8];
#pragma unroll
    for (int o = 16; o; o >>= 1) {
        s  += __shfl_xor_sync(0xffffffffu, s,  o);
        ss += __shfl_xor_sync(0xffffffffu, ss, o);
    }
    if ((tid & 31) == 0) { rs[tid >> 5] = s; rss[tid >> 5] = ss; }
    __syncthreads();
    if (tid == 0) {
        float S = 0.f, SS = 0.f;
#pragma unroll
        for (int i = 0; i < 8; i++) { S += rs[i]; SS += rss[i]; }
        rs[0] = S; rss[0] = SS;
    }
    __syncthreads();
    float mu  = rs[0]  * (1.0f / 768.0f);
    float var = rss[0] * (1.0f / 768.0f) - mu * mu;
    float inv = rsqrtf(var + 1e-5f);

    float* o = out + (size_t)row * Hz;
    o[tid]       = (v0 - mu) * inv * gamma[tid]       + beta[tid];
    o[tid + 256] = (v1 - mu) * inv * gamma[tid + 256] + beta[tid + 256];
    o[tid + 512] = (v2 - mu) * inv * gamma[tid + 512] + beta[tid + 512];
}

// -------------------- avg_weights == 1/3 analytically --------------------
__global__ void __launch_bounds__(256)
fill_third(float* __restrict__ p)
{
    size_t i = (size_t)blockIdx.x * 256 + threadIdx.x;
    const float t = 1.0f / 3.0f;
    ((float4*)p)[i] = make_float4(t, t, t, t);
}

// -------------------- launch --------------------
extern "C" void kernel_launch(void* const* d_in, const int* in_sizes, int n_in,
                              void* d_out, int out_size)
{
    const float* query = (const float*)d_in[0];
    const float* adap  = (const float*)d_in[1];
    const float* Wq    = (const float*)d_in[2];
    const float* bq    = (const float*)d_in[3];
    const float* Wk    = (const float*)d_in[4];
    const float* bk    = (const float*)d_in[5];
    const float* Wv    = (const float*)d_in[6];
    const float* bv    = (const float*)d_in[7];
    const float* Wo    = (const float*)d_in[8];
    const float* bo    = (const float*)d_in[9];
    const float* gamma = (const float*)d_in[10];
    const float* beta  = (const float*)d_in[11];

    float* out = (float*)d_out;
    float* avg = out + (size_t)Bz * Sz * Hz;

    const int SMEM_ATTN = 5 * 64 * 68 * 4;   // 87040 B
    static bool attr_set = false;
    (void)attr_set;
    cudaFuncSetAttribute(attn_kernel, cudaFuncAttributeMaxDynamicSharedMemorySize, SMEM_ATTN);

    dim3 blk(256);

    // avg_weights = 1/3 (independent of everything else)
    fill_third<<<(Bz * Sz * Sz) / 4 / 256, blk>>>(avg);

    // projections
    gemm_proj<0><<<dim3(Hz / 64, (Bz * Sz) / 64),        blk>>>(query, Wq, bq, nullptr);
    gemm_proj<1><<<dim3(Hz / 64, (Bz * Az * Sz) / 64),   blk>>>(adap,  Wk, bk, nullptr);
    gemm_proj<2><<<dim3(Hz / 64, (Bz * Az * Sz) / 64),   blk>>>(adap,  Wv, bv, nullptr);

    // attention
    attn_kernel<<<dim3(Sz / 64, NHz, Bz), blk, SMEM_ATTN>>>();

    // output projection + residual, then LayerNorm
    gemm_proj<3><<<dim3(Hz / 64, (Bz * Sz) / 64), blk>>>(nullptr, Wo, bo, query);
    ln_kernel<<<Bz * Sz, blk>>>(gamma, beta, out);
}

// round 3
// speedup vs baseline: 1.4855x; 1.4855x over previous
#include <cuda_runtime.h>
#include <cuda_bf16.h>
#include <cstdint>

// Problem constants
#define Bz   4
#define Az   3
#define Sz   1024
#define Hz   768
#define NHz  12
#define HDz  64

// -------------------- scratch (device globals; no allocation) --------------------
__device__ float g_Q  [Bz*NHz*Sz*HDz];        // [b][h][s][d], pre-scaled by 1/8
__device__ float g_K  [Bz*NHz*Az*Sz*HDz];     // [b][h][a][s][d]
__device__ float g_V  [Bz*NHz*Az*Sz*HDz];     // [b][h][a][s][d]
__device__ float g_att[Bz*Sz*Hz];             // attended, [b][s][h*64+d]
__device__ float g_res[Bz*Sz*Hz];             // attended@Wo^T + bo + query (pre-LN)

typedef unsigned long long u64;

// SW64 swizzle for 64-byte SMEM rows (conflict-free for ldmatrix + STS.64)
#define SWZ64(o) ((o) ^ (((o) >> 3) & 0x30))

__device__ __forceinline__ uint32_t smem_u32(const void* p) {
    uint32_t a;
    asm("{ .reg .u64 t; cvta.to.shared.u64 t, %1; cvt.u32.u64 %0, t; }"
        : "=r"(a) : "l"(p));
    return a;
}
__device__ __forceinline__ void ldsm_x4(uint32_t* f, uint32_t a) {
    asm volatile("ldmatrix.sync.aligned.m8n8.x4.shared.b16 {%0,%1,%2,%3}, [%4];"
                 : "=r"(f[0]), "=r"(f[1]), "=r"(f[2]), "=r"(f[3]) : "r"(a));
}
__device__ __forceinline__ void mma16816(float* d, const uint32_t* a, const uint32_t* b) {
    asm volatile("mma.sync.aligned.m16n8k16.row.col.f32.bf16.bf16.f32 "
                 "{%0,%1,%2,%3}, {%4,%5,%6,%7}, {%8,%9}, {%0,%1,%2,%3};"
                 : "+f"(d[0]), "+f"(d[1]), "+f"(d[2]), "+f"(d[3])
                 : "r"(a[0]), "r"(a[1]), "r"(a[2]), "r"(a[3]), "r"(b[0]), "r"(b[1]));
}

// fp32 float4 -> (bf16 hi x4, bf16 lo x4) packed as 2x uint2
__device__ __forceinline__ void cvt_split(float4 v, uint2& hi, uint2& lo) {
    uint32_t h0, h1;
    asm("cvt.rn.bf16x2.f32 %0, %1, %2;" : "=r"(h0) : "f"(v.y), "f"(v.x));
    asm("cvt.rn.bf16x2.f32 %0, %1, %2;" : "=r"(h1) : "f"(v.w), "f"(v.z));
    float hx = __uint_as_float(h0 << 16);
    float hy = __uint_as_float(h0 & 0xffff0000u);
    float hz = __uint_as_float(h1 << 16);
    float hw = __uint_as_float(h1 & 0xffff0000u);
    uint32_t l0, l1;
    asm("cvt.rn.bf16x2.f32 %0, %1, %2;" : "=r"(l0) : "f"(v.y - hy), "f"(v.x - hx));
    asm("cvt.rn.bf16x2.f32 %0, %1, %2;" : "=r"(l1) : "f"(v.w - hw), "f"(v.z - hz));
    hi = make_uint2(h0, h1);
    lo = make_uint2(l0, l1);
}

// ==================== mma.sync projection GEMM ====================
// out[m][n] = sum_k X[m][k] * W[n][k]  (+bias, mode scatter)
// CTA tile 128x128, warps 2x4 (each 64x32), K staged 32 at a time, double buffer.
// SMEM per buffer: Ahi(8K) Alo(8K) Bhi(8K) Blo(8K) = 32KB; x2 = 64KB.
// MODE 0: X=query   -> g_Q (val*0.125, head layout)
// MODE 1: X=adapter -> g_K   MODE 2: X=adapter -> g_V
// MODE 3: X=g_att   -> g_res (+ bias + residual)
#define GMM_SMEM (2 * 32768)

template <int MODE>
__device__ __forceinline__ void store_stage(char* sm, uint32_t bufoff, int lr, int lc,
                                            const float4* aR, const float4* bR)
{
#pragma unroll
    for (int i = 0; i < 4; i++) {
        uint2 hi, lo; cvt_split(aR[i], hi, lo);
        uint32_t off = SWZ64((uint32_t)(lr + 32 * i) * 64u + (uint32_t)lc * 8u);
        *(uint2*)(sm + bufoff + off)        = hi;
        *(uint2*)(sm + bufoff + 8192 + off) = lo;
    }
#pragma unroll
    for (int i = 0; i < 4; i++) {
        uint2 hi, lo; cvt_split(bR[i], hi, lo);
        uint32_t off = SWZ64((uint32_t)(lr + 32 * i) * 64u + (uint32_t)lc * 8u);
        *(uint2*)(sm + bufoff + 16384 + off) = hi;
        *(uint2*)(sm + bufoff + 24576 + off) = lo;
    }
}

template <int MODE>
__global__ void __launch_bounds__(256)
gemm_mma(const float* __restrict__ X, const float* __restrict__ W,
         const float* __restrict__ bias, const float* __restrict__ resid)
{
    extern __shared__ char sm[];
    const uint32_t sb = smem_u32(sm);
    const int tid = threadIdx.x, lane = tid & 31, w = tid >> 5;
    const int wm = w >> 2, wn = w & 3;          // warp grid 2 x 4
    const int m0 = blockIdx.x * 128, n0 = blockIdx.y * 128;

    const float* Xs = (MODE == 3) ? (const float*)g_att : X;

    // loader: 256 threads, each row lr (0..31) chunk lc (0..7, float4)
    const int lr = tid >> 3, lc = tid & 7;
    const float* Ag = Xs + (size_t)(m0 + lr) * Hz + lc * 4;
    const float* Bg = W  + (size_t)(n0 + lr) * Hz + lc * 4;

    float4 aR[4], bR[4];
#pragma unroll
    for (int i = 0; i < 4; i++) aR[i] = *(const float4*)(Ag + (size_t)i * 32 * Hz);
#pragma unroll
    for (int i = 0; i < 4; i++) bR[i] = *(const float4*)(Bg + (size_t)i * 32 * Hz);
    store_stage<MODE>(sm, 0, lr, lc, aR, bR);
    __syncthreads();

    float acc[4][4][4];
#pragma unroll
    for (int a = 0; a < 4; a++)
#pragma unroll
        for (int b = 0; b < 4; b++)
#pragma unroll
            for (int c = 0; c < 4; c++) acc[a][b][c] = 0.0f;

    // ldmatrix lane address components
    const int arow = lane & 15;                    // A: rows 0-15 of m16 tile
    const int akb  = (lane >> 4) << 4;             // A: k-byte 0/16
    const int brow = (lane & 7) + ((lane & 16) >> 1);  // B: n row (+8 for lanes 16-31)
    const int bkb  = (lane & 8) << 1;              // B: k-byte 0/16

    for (int s = 0; s < 24; s++) {
        const uint32_t base = sb + (uint32_t)(s & 1) * 32768u;

        if (s < 23) {
            const int ko = (s + 1) * 32;
#pragma unroll
            for (int i = 0; i < 4; i++) aR[i] = *(const float4*)(Ag + (size_t)i * 32 * Hz + ko);
#pragma unroll
            for (int i = 0; i < 4; i++) bR[i] = *(const float4*)(Bg + (size_t)i * 32 * Hz + ko);
        }

#pragma unroll
        for (int k16 = 0; k16 < 2; k16++) {
            const int kof = k16 * 32;
            uint32_t fa[4][4], fbh[2][4], fbl[2][4];
#pragma unroll
            for (int mi = 0; mi < 4; mi++) {
                uint32_t off = (uint32_t)((wm * 64 + mi * 16 + arow) * 64 + kof + akb);
                ldsm_x4(fa[mi], base + SWZ64(off));                 // A hi
            }
#pragma unroll
            for (int ni = 0; ni < 2; ni++) {
                uint32_t off = (uint32_t)((wn * 32 + ni * 16 + brow) * 64 + kof + bkb);
                ldsm_x4(fbh[ni], base + 16384 + SWZ64(off));        // B hi
                ldsm_x4(fbl[ni], base + 24576 + SWZ64(off));        // B lo
            }
            // pass 0: Ahi*Bhi, pass 1: Ahi*Blo
#pragma unroll
            for (int mi = 0; mi < 4; mi++)
#pragma unroll
                for (int ni = 0; ni < 4; ni++) {
                    mma16816(acc[mi][ni], fa[mi], &fbh[ni >> 1][(ni & 1) * 2]);
                    mma16816(acc[mi][ni], fa[mi], &fbl[ni >> 1][(ni & 1) * 2]);
                }
            // pass 2: Alo*Bhi (reuse fa regs)
#pragma unroll
            for (int mi = 0; mi < 4; mi++) {
                uint32_t off = (uint32_t)((wm * 64 + mi * 16 + arow) * 64 + kof + akb);
                ldsm_x4(fa[mi], base + 8192 + SWZ64(off));          // A lo
            }
#pragma unroll
            for (int mi = 0; mi < 4; mi++)
#pragma unroll
                for (int ni = 0; ni < 4; ni++)
                    mma16816(acc[mi][ni], fa[mi], &fbh[ni >> 1][(ni & 1) * 2]);
        }

        if (s < 23)
            store_stage<MODE>(sm, (uint32_t)((s + 1) & 1) * 32768u, lr, lc, aR, bR);
        __syncthreads();
    }

    // ---- epilogue ----
    const int g = lane >> 2, t = lane & 3;
#pragma unroll
    for (int ni = 0; ni < 4; ni++) {
        const int col = n0 + wn * 32 + ni * 8 + 2 * t;
        const float2 bs = *(const float2*)(bias + col);
#pragma unroll
        for (int mi = 0; mi < 4; mi++) {
            const int r0 = m0 + wm * 64 + mi * 16 + g;
#pragma unroll
            for (int half = 0; half < 2; half++) {
                const int row = r0 + half * 8;
                float vx = acc[mi][ni][half * 2 + 0] + bs.x;
                float vy = acc[mi][ni][half * 2 + 1] + bs.y;
                if (MODE == 0) {
                    const int b = row >> 10, ss = row & 1023;
                    const int h = col >> 6, d = col & 63;
                    float* dst = g_Q + (((size_t)(b * NHz + h)) * Sz + ss) * HDz + d;
                    *(float2*)dst = make_float2(vx * 0.125f, vy * 0.125f);
                } else if (MODE == 1 || MODE == 2) {
                    const int b = row / (Az * Sz), rr = row - b * (Az * Sz);
                    const int a = rr >> 10, ss = rr & 1023;
                    const int h = col >> 6, d = col & 63;
                    float* bsd = (MODE == 1) ? g_K : g_V;
                    float* dst = bsd + ((((size_t)(b * NHz + h)) * Az + a) * Sz + ss) * HDz + d;
                    *(float2*)dst = make_float2(vx, vy);
                } else {
                    const float2 q = *(const float2*)(resid + (size_t)row * Hz + col);
                    *(float2*)(g_res + (size_t)row * Hz + col)
                        = make_float2(vx + q.x, vy + q.y);
                }
            }
        }
    }
}

// -------------------- packed f32x2 helpers --------------------
__device__ __forceinline__ u64 pk2(float lo, float hi) {
    u64 r; asm("mov.b64 %0, {%1,%2};" : "=l"(r) : "f"(lo), "f"(hi)); return r;
}
__device__ __forceinline__ void upk2(u64 v, float& lo, float& hi) {
    asm("mov.b64 {%0,%1}, %2;" : "=f"(lo), "=f"(hi) : "l"(v));
}
__device__ __forceinline__ void fma2(u64& d, u64 a, u64 b) {
    asm("fma.rn.f32x2 %0, %1, %2, %0;" : "+l"(d) : "l"(a), "l"(b));
}

// -------------------- fast exp2 / rcp --------------------
__device__ __forceinline__ float fexp2(float x) {
    x = fmaxf(x, -120.0f);
    float n = floorf(x);
    float f = x - n;
    float p =             1.5404e-4f;
    p = fmaf(p, f, 1.3333558e-3f);
    p = fmaf(p, f, 9.6181291e-3f);
    p = fmaf(p, f, 5.5504109e-2f);
    p = fmaf(p, f, 2.4022651e-1f);
    p = fmaf(p, f, 6.9314718e-1f);
    p = fmaf(p, f, 1.0f);
    int e = (int)n;
    float sc = __int_as_float((e + 127) << 23);
    return p * sc;
}
__device__ __forceinline__ float frcp(float s) {
    float x = __int_as_float(0x7EF311C3u - __float_as_int(s));
    x = x * fmaf(-s, x, 2.0f);
    x = x * fmaf(-s, x, 2.0f);
    x = x * fmaf(-s, x, 2.0f);
    return x;
}
__device__ __forceinline__ void softmax3(float& a, float& b, float& c) {
    const float L2E = 1.4426950408889634f;
    float m  = fmaxf(a, fmaxf(b, c));
    float mL = m * L2E;
    float e0 = fexp2(fmaf(a, L2E, -mL));
    float e1 = fexp2(fmaf(b, L2E, -mL));
    float e2 = fexp2(fmaf(c, L2E, -mL));
    float r  = frcp(e0 + e1 + e2);
    a = e0 * r; b = e1 * r; c = e2 * r;
}

// -------------------- fused attention (R1, FFMA2) --------------------
__global__ void __launch_bounds__(256)
attn_kernel()
{
    extern __shared__ float smem[];
    float (*Qs)[68]     = (float(*)[68])     (smem);
    float (*Ks)[68]     = (float(*)[68])     (smem + 4352);
    float (*Ps)[64][68] = (float(*)[64][68]) (smem + 8704);

    const int tid = threadIdx.x;
    const int tx  = tid & 15, ty = tid >> 4;
    const int b   = blockIdx.z, h = blockIdx.y, q0 = blockIdx.x * 64;

    const float* Qg = g_Q + ((size_t)(b * NHz + h)) * Sz * HDz;
    const float* Kg = g_K + ((size_t)(b * NHz + h)) * Az * Sz * HDz;
    const float* Vg = g_V + ((size_t)(b * NHz + h)) * Az * Sz * HDz;

    const int row = tid >> 2;

#pragma unroll
    for (int r = 0; r < 4; r++) {
        int dq = ((tid & 3) + 4 * r) * 4;
        float4 v = *(const float4*)(Qg + (size_t)(q0 + row) * HDz + dq);
        Qs[dq+0][row] = v.x; Qs[dq+1][row] = v.y; Qs[dq+2][row] = v.z; Qs[dq+3][row] = v.w;
    }

    u64 att[4][2];
#pragma unroll
    for (int i = 0; i < 4; i++) { att[i][0] = 0ULL; att[i][1] = 0ULL; }

    __syncthreads();

    for (int s0 = 0; s0 < Sz; s0 += 64) {
        for (int a = 0; a < 3; a++) {
            float4 kv[4];
#pragma unroll
            for (int r = 0; r < 4; r++) {
                int dq = ((tid & 3) + 4 * r) * 4;
                kv[r] = *(const float4*)(Kg + ((size_t)a * Sz + s0 + row) * HDz + dq);
            }
            __syncthreads();
#pragma unroll
            for (int r = 0; r < 4; r++) {
                int dq = ((tid & 3) + 4 * r) * 4;
                Ks[dq+0][row] = kv[r].x; Ks[dq+1][row] = kv[r].y;
                Ks[dq+2][row] = kv[r].z; Ks[dq+3][row] = kv[r].w;
            }
            __syncthreads();

            u64 sc[4][2];
#pragma unroll
            for (int i = 0; i < 4; i++) { sc[i][0] = 0ULL; sc[i][1] = 0ULL; }
#pragma unroll 16
            for (int kk = 0; kk < 64; kk++) {
                float4     q4 = *(const float4*)    &Qs[kk][ty * 4];
                ulonglong2 k2 = *(const ulonglong2*)&Ks[kk][tx * 4];
                u64 d0 = pk2(q4.x, q4.x), d1 = pk2(q4.y, q4.y);
                u64 d2 = pk2(q4.z, q4.z), d3 = pk2(q4.w, q4.w);
                fma2(sc[0][0], d0, k2.x); fma2(sc[0][1], d0, k2.y);
                fma2(sc[1][0], d1, k2.x); fma2(sc[1][1], d1, k2.y);
                fma2(sc[2][0], d2, k2.x); fma2(sc[2][1], d2, k2.y);
                fma2(sc[3][0], d3, k2.x); fma2(sc[3][1], d3, k2.y);
            }
#pragma unroll
            for (int i = 0; i < 4; i++) {
                float w0, w1, w2, w3;
                upk2(sc[i][0], w0, w1); upk2(sc[i][1], w2, w3);
                *(float4*)&Ps[a][ty * 4 + i][tx * 4] = make_float4(w0, w1, w2, w3);
            }
        }

#pragma unroll
        for (int i = 0; i < 4; i++) {
            int q = ty * 4 + i, c = tx * 4;
            float4 A  = *(float4*)&Ps[0][q][c];
            float4 Bv = *(float4*)&Ps[1][q][c];
            float4 C  = *(float4*)&Ps[2][q][c];
            softmax3(A.x, Bv.x, C.x);
            softmax3(A.y, Bv.y, C.y);
            softmax3(A.z, Bv.z, C.z);
            softmax3(A.w, Bv.w, C.w);
            *(float4*)&Ps[0][q][c] = A;
            *(float4*)&Ps[1][q][c] = Bv;
            *(float4*)&Ps[2][q][c] = C;
        }
        __syncthreads();

        for (int a = 0; a < 3; a++) {
            float4 vv[4];
#pragma unroll
            for (int r = 0; r < 4; r++) {
                int dq = ((tid & 3) + 4 * r) * 4;
                vv[r] = *(const float4*)(Vg + ((size_t)a * Sz + s0 + row) * HDz + dq);
            }
            __syncthreads();
#pragma unroll
            for (int r = 0; r < 4; r++) {
                int dq = ((tid & 3) + 4 * r) * 4;
                *(float4*)&Ks[row][dq] = vv[r];
            }
            __syncthreads();
#pragma unroll 16
            for (int kk = 0; kk < 64; kk++) {
                ulonglong2 v2 = *(const ulonglong2*)&Ks[kk][tx * 4];
                float p0 = Ps[a][ty * 4 + 0][kk];
                float p1 = Ps[a][ty * 4 + 1][kk];
                float p2 = Ps[a][ty * 4 + 2][kk];
                float p3 = Ps[a][ty * 4 + 3][kk];
                u64 d0 = pk2(p0, p0), d1 = pk2(p1, p1);
                u64 d2 = pk2(p2, p2), d3 = pk2(p3, p3);
                fma2(att[0][0], d0, v2.x); fma2(att[0][1], d0, v2.y);
                fma2(att[1][0], d1, v2.x); fma2(att[1][1], d1, v2.y);
                fma2(att[2][0], d2, v2.x); fma2(att[2][1], d2, v2.y);
                fma2(att[3][0], d3, v2.x); fma2(att[3][1], d3, v2.y);
            }
        }
        __syncthreads();
    }

#pragma unroll
    for (int i = 0; i < 4; i++) {
        float w0, w1, w2, w3;
        upk2(att[i][0], w0, w1); upk2(att[i][1], w2, w3);
        *(float4*)(g_att + ((size_t)b * Sz + q0 + ty * 4 + i) * Hz + h * 64 + tx * 4)
            = make_float4(w0, w1, w2, w3);
    }
}

// -------------------- LayerNorm over H=768 per row --------------------
__global__ void __launch_bounds__(256)
ln_kernel(const float* __restrict__ gamma, const float* __restrict__ beta,
          float* __restrict__ out)
{
    const int row = blockIdx.x;
    const int tid = threadIdx.x;
    const float* x = g_res + (size_t)row * Hz;

    float v0 = x[tid], v1 = x[tid + 256], v2 = x[tid + 512];
    float s  = v0 + v1 + v2;
    float ss = v0 * v0 + v1 * v1 + v2 * v2;

    __shared__ float rs[8], rss[8];
#pragma unroll
    for (int o = 16; o; o >>= 1) {
        s  += __shfl_xor_sync(0xffffffffu, s,  o);
        ss += __shfl_xor_sync(0xffffffffu, ss, o);
    }
    if ((tid & 31) == 0) { rs[tid >> 5] = s; rss[tid >> 5] = ss; }
    __syncthreads();
    if (tid == 0) {
        float S = 0.f, SS = 0.f;
#pragma unroll
        for (int i = 0; i < 8; i++) { S += rs[i]; SS += rss[i]; }
        rs[0] = S; rss[0] = SS;
    }
    __syncthreads();
    float mu  = rs[0]  * (1.0f / 768.0f);
    float var = rss[0] * (1.0f / 768.0f) - mu * mu;
    float inv = rsqrtf(var + 1e-5f);

    float* o = out + (size_t)row * Hz;
    o[tid]       = (v0 - mu) * inv * gamma[tid]       + beta[tid];
    o[tid + 256] = (v1 - mu) * inv * gamma[tid + 256] + beta[tid + 256];
    o[tid + 512] = (v2 - mu) * inv * gamma[tid + 512] + beta[tid + 512];
}

// -------------------- avg_weights == 1/3 analytically --------------------
__global__ void __launch_bounds__(256)
fill_third(float* __restrict__ p)
{
    size_t i = (size_t)blockIdx.x * 256 + threadIdx.x;
    const float t = 1.0f / 3.0f;
    ((float4*)p)[i] = make_float4(t, t, t, t);
}

// -------------------- launch --------------------
extern "C" void kernel_launch(void* const* d_in, const int* in_sizes, int n_in,
                              void* d_out, int out_size)
{
    const float* query = (const float*)d_in[0];
    const float* adap  = (const float*)d_in[1];
    const float* Wq    = (const float*)d_in[2];
    const float* bq    = (const float*)d_in[3];
    const float* Wk    = (const float*)d_in[4];
    const float* bk    = (const float*)d_in[5];
    const float* Wv    = (const float*)d_in[6];
    const float* bv    = (const float*)d_in[7];
    const float* Wo    = (const float*)d_in[8];
    const float* bo    = (const float*)d_in[9];
    const float* gamma = (const float*)d_in[10];
    const float* beta  = (const float*)d_in[11];

    float* out = (float*)d_out;
    float* avg = out + (size_t)Bz * Sz * Hz;

    const int SMEM_ATTN = 5 * 64 * 68 * 4;   // 87040 B
    cudaFuncSetAttribute(attn_kernel, cudaFuncAttributeMaxDynamicSharedMemorySize, SMEM_ATTN);
    cudaFuncSetAttribute(gemm_mma<0>, cudaFuncAttributeMaxDynamicSharedMemorySize, GMM_SMEM);
    cudaFuncSetAttribute(gemm_mma<1>, cudaFuncAttributeMaxDynamicSharedMemorySize, GMM_SMEM);
    cudaFuncSetAttribute(gemm_mma<2>, cudaFuncAttributeMaxDynamicSharedMemorySize, GMM_SMEM);
    cudaFuncSetAttribute(gemm_mma<3>, cudaFuncAttributeMaxDynamicSharedMemorySize, GMM_SMEM);

    dim3 blk(256);

    // avg_weights = 1/3
    fill_third<<<(Bz * Sz * Sz) / 4 / 256, blk>>>(avg);

    // projections (mma.sync bf16, 2-term split)
    gemm_mma<0><<<dim3((Bz * Sz) / 128, Hz / 128),      blk, GMM_SMEM>>>(query, Wq, bq, nullptr);
    gemm_mma<1><<<dim3((Bz * Az * Sz) / 128, Hz / 128), blk, GMM_SMEM>>>(adap,  Wk, bk, nullptr);
    gemm_mma<2><<<dim3((Bz * Az * Sz) / 128, Hz / 128), blk, GMM_SMEM>>>(adap,  Wv, bv, nullptr);

    // attention
    attn_kernel<<<dim3(Sz / 64, NHz, Bz), blk, SMEM_ATTN>>>();

    // output projection + residual, then LayerNorm
    gemm_mma<3><<<dim3((Bz * Sz) / 128, Hz / 128), blk, GMM_SMEM>>>(nullptr, Wo, bo, query);
    ln_kernel<<<Bz * Sz, blk>>>(gamma, beta, out);
}

// round 4
// speedup vs baseline: 2.5051x; 1.6864x over previous
#include <cuda_runtime.h>
#include <cuda_bf16.h>
#include <cstdint>

// Problem constants
#define Bz   4
#define Az   3
#define Sz   1024
#define Hz   768
#define NHz  12
#define HDz  64

// -------------------- scratch (device globals; no allocation) --------------------
__device__ float g_Q  [Bz*NHz*Sz*HDz];        // [b][h][s][d], pre-scaled by 1/8
__device__ float g_K  [Bz*NHz*Az*Sz*HDz];     // [b][h][a][s][d]
__device__ float g_Vt [Bz*NHz*Az*HDz*Sz];     // [b][h][a][d][s]  (transposed!)
__device__ float g_att[Bz*Sz*Hz];             // attended, [b][s][h*64+d]
__device__ float g_res[Bz*Sz*Hz];             // attended@Wo^T + bo + query (pre-LN)

typedef unsigned long long u64;

// SW64 swizzle for 64-byte SMEM rows (conflict-free for ldmatrix + STS.64)
#define SWZ64(o) ((o) ^ (((o) >> 3) & 0x30))

__device__ __forceinline__ uint32_t smem_u32(const void* p) {
    uint32_t a;
    asm("{ .reg .u64 t; cvta.to.shared.u64 t, %1; cvt.u32.u64 %0, t; }"
        : "=r"(a) : "l"(p));
    return a;
}
__device__ __forceinline__ void ldsm_x4(uint32_t* f, uint32_t a) {
    asm volatile("ldmatrix.sync.aligned.m8n8.x4.shared.b16 {%0,%1,%2,%3}, [%4];"
                 : "=r"(f[0]), "=r"(f[1]), "=r"(f[2]), "=r"(f[3]) : "r"(a));
}
__device__ __forceinline__ void mma16816(float* d, const uint32_t* a, const uint32_t* b) {
    asm volatile("mma.sync.aligned.m16n8k16.row.col.f32.bf16.bf16.f32 "
                 "{%0,%1,%2,%3}, {%4,%5,%6,%7}, {%8,%9}, {%0,%1,%2,%3};"
                 : "+f"(d[0]), "+f"(d[1]), "+f"(d[2]), "+f"(d[3])
                 : "r"(a[0]), "r"(a[1]), "r"(a[2]), "r"(a[3]), "r"(b[0]), "r"(b[1]));
}

// fp32 float4 -> (bf16 hi x4, bf16 lo x4) packed as 2x uint2
__device__ __forceinline__ void cvt_split(float4 v, uint2& hi, uint2& lo) {
    uint32_t h0, h1;
    asm("cvt.rn.bf16x2.f32 %0, %1, %2;" : "=r"(h0) : "f"(v.y), "f"(v.x));
    asm("cvt.rn.bf16x2.f32 %0, %1, %2;" : "=r"(h1) : "f"(v.w), "f"(v.z));
    float hx = __uint_as_float(h0 << 16);
    float hy = __uint_as_float(h0 & 0xffff0000u);
    float hz = __uint_as_float(h1 << 16);
    float hw = __uint_as_float(h1 & 0xffff0000u);
    uint32_t l0, l1;
    asm("cvt.rn.bf16x2.f32 %0, %1, %2;" : "=r"(l0) : "f"(v.y - hy), "f"(v.x - hx));
    asm("cvt.rn.bf16x2.f32 %0, %1, %2;" : "=r"(l1) : "f"(v.w - hw), "f"(v.z - hz));
    hi = make_uint2(h0, h1);
    lo = make_uint2(l0, l1);
}
// fp32 pair -> bf16x2 hi + bf16x2 lo
__device__ __forceinline__ void split2(float x, float y, uint32_t& hi, uint32_t& lo) {
    asm("cvt.rn.bf16x2.f32 %0, %1, %2;" : "=r"(hi) : "f"(y), "f"(x));
    float hx = __uint_as_float(hi << 16);
    float hy = __uint_as_float(hi & 0xffff0000u);
    asm("cvt.rn.bf16x2.f32 %0, %1, %2;" : "=r"(lo) : "f"(y - hy), "f"(x - hx));
}

// ==================== mma.sync projection GEMM (R3, validated) ====================
#define GMM_SMEM (2 * 32768)

template <int MODE>
__device__ __forceinline__ void store_stage(char* sm, uint32_t bufoff, int lr, int lc,
                                            const float4* aR, const float4* bR)
{
#pragma unroll
    for (int i = 0; i < 4; i++) {
        uint2 hi, lo; cvt_split(aR[i], hi, lo);
        uint32_t off = SWZ64((uint32_t)(lr + 32 * i) * 64u + (uint32_t)lc * 8u);
        *(uint2*)(sm + bufoff + off)        = hi;
        *(uint2*)(sm + bufoff + 8192 + off) = lo;
    }
#pragma unroll
    for (int i = 0; i < 4; i++) {
        uint2 hi, lo; cvt_split(bR[i], hi, lo);
        uint32_t off = SWZ64((uint32_t)(lr + 32 * i) * 64u + (uint32_t)lc * 8u);
        *(uint2*)(sm + bufoff + 16384 + off) = hi;
        *(uint2*)(sm + bufoff + 24576 + off) = lo;
    }
}

template <int MODE>
__global__ void __launch_bounds__(256)
gemm_mma(const float* __restrict__ X, const float* __restrict__ W,
         const float* __restrict__ bias, const float* __restrict__ resid)
{
    extern __shared__ char sm[];
    const uint32_t sb = smem_u32(sm);
    const int tid = threadIdx.x, lane = tid & 31, w = tid >> 5;
    const int wm = w >> 2, wn = w & 3;
    const int m0 = blockIdx.x * 128, n0 = blockIdx.y * 128;

    const float* Xs = (MODE == 3) ? (const float*)g_att : X;

    const int lr = tid >> 3, lc = tid & 7;
    const float* Ag = Xs + (size_t)(m0 + lr) * Hz + lc * 4;
    const float* Bg = W  + (size_t)(n0 + lr) * Hz + lc * 4;

    float4 aR[4], bR[4];
#pragma unroll
    for (int i = 0; i < 4; i++) aR[i] = *(const float4*)(Ag + (size_t)i * 32 * Hz);
#pragma unroll
    for (int i = 0; i < 4; i++) bR[i] = *(const float4*)(Bg + (size_t)i * 32 * Hz);
    store_stage<MODE>(sm, 0, lr, lc, aR, bR);
    __syncthreads();

    float acc[4][4][4];
#pragma unroll
    for (int a = 0; a < 4; a++)
#pragma unroll
        for (int b = 0; b < 4; b++)
#pragma unroll
            for (int c = 0; c < 4; c++) acc[a][b][c] = 0.0f;

    const int arow = lane & 15;
    const int akb  = (lane >> 4) << 4;
    const int brow = (lane & 7) + ((lane & 16) >> 1);
    const int bkb  = (lane & 8) << 1;

    for (int s = 0; s < 24; s++) {
        const uint32_t base = sb + (uint32_t)(s & 1) * 32768u;

        if (s < 23) {
            const int ko = (s + 1) * 32;
#pragma unroll
            for (int i = 0; i < 4; i++) aR[i] = *(const float4*)(Ag + (size_t)i * 32 * Hz + ko);
#pragma unroll
            for (int i = 0; i < 4; i++) bR[i] = *(const float4*)(Bg + (size_t)i * 32 * Hz + ko);
        }

#pragma unroll
        for (int k16 = 0; k16 < 2; k16++) {
            const int kof = k16 * 32;
            uint32_t fa[4][4], fbh[2][4], fbl[2][4];
#pragma unroll
            for (int mi = 0; mi < 4; mi++) {
                uint32_t off = (uint32_t)((wm * 64 + mi * 16 + arow) * 64 + kof + akb);
                ldsm_x4(fa[mi], base + SWZ64(off));
            }
#pragma unroll
            for (int ni = 0; ni < 2; ni++) {
                uint32_t off = (uint32_t)((wn * 32 + ni * 16 + brow) * 64 + kof + bkb);
                ldsm_x4(fbh[ni], base + 16384 + SWZ64(off));
                ldsm_x4(fbl[ni], base + 24576 + SWZ64(off));
            }
#pragma unroll
            for (int mi = 0; mi < 4; mi++)
#pragma unroll
                for (int ni = 0; ni < 4; ni++) {
                    mma16816(acc[mi][ni], fa[mi], &fbh[ni >> 1][(ni & 1) * 2]);
                    mma16816(acc[mi][ni], fa[mi], &fbl[ni >> 1][(ni & 1) * 2]);
                }
#pragma unroll
            for (int mi = 0; mi < 4; mi++) {
                uint32_t off = (uint32_t)((wm * 64 + mi * 16 + arow) * 64 + kof + akb);
                ldsm_x4(fa[mi], base + 8192 + SWZ64(off));
            }
#pragma unroll
            for (int mi = 0; mi < 4; mi++)
#pragma unroll
                for (int ni = 0; ni < 4; ni++)
                    mma16816(acc[mi][ni], fa[mi], &fbh[ni >> 1][(ni & 1) * 2]);
        }

        if (s < 23)
            store_stage<MODE>(sm, (uint32_t)((s + 1) & 1) * 32768u, lr, lc, aR, bR);
        __syncthreads();
    }

    // ---- epilogue ----
    const int g = lane >> 2, t = lane & 3;
#pragma unroll
    for (int ni = 0; ni < 4; ni++) {
        const int col = n0 + wn * 32 + ni * 8 + 2 * t;
        const float2 bs = *(const float2*)(bias + col);
#pragma unroll
        for (int mi = 0; mi < 4; mi++) {
            const int r0 = m0 + wm * 64 + mi * 16 + g;
#pragma unroll
            for (int half = 0; half < 2; half++) {
                const int row = r0 + half * 8;
                float vx = acc[mi][ni][half * 2 + 0] + bs.x;
                float vy = acc[mi][ni][half * 2 + 1] + bs.y;
                if (MODE == 0) {
                    const int b = row >> 10, ss = row & 1023;
                    const int h = col >> 6, d = col & 63;
                    float* dst = g_Q + (((size_t)(b * NHz + h)) * Sz + ss) * HDz + d;
                    *(float2*)dst = make_float2(vx * 0.125f, vy * 0.125f);
                } else if (MODE == 1) {
                    const int b = row / (Az * Sz), rr = row - b * (Az * Sz);
                    const int a = rr >> 10, ss = rr & 1023;
                    const int h = col >> 6, d = col & 63;
                    float* dst = g_K + ((((size_t)(b * NHz + h)) * Az + a) * Sz + ss) * HDz + d;
                    *(float2*)dst = make_float2(vx, vy);
                } else if (MODE == 2) {
                    // transposed V: [b][h][a][d][s]
                    const int b = row / (Az * Sz), rr = row - b * (Az * Sz);
                    const int a = rr >> 10, ss = rr & 1023;
                    const int h = col >> 6, d = col & 63;
                    float* dst = g_Vt + ((((size_t)(b * NHz + h)) * Az + a) * HDz + d) * Sz + ss;
                    dst[0]  = vx;
                    dst[Sz] = vy;
                } else {
                    const float2 q = *(const float2*)(resid + (size_t)row * Hz + col);
                    *(float2*)(g_res + (size_t)row * Hz + col)
                        = make_float2(vx + q.x, vy + q.y);
                }
            }
        }
    }
}

// -------------------- fast exp2 / rcp --------------------
__device__ __forceinline__ float fexp2(float x) {
    x = fmaxf(x, -120.0f);
    float n = floorf(x);
    float f = x - n;
    float p =             1.5404e-4f;
    p = fmaf(p, f, 1.3333558e-3f);
    p = fmaf(p, f, 9.6181291e-3f);
    p = fmaf(p, f, 5.5504109e-2f);
    p = fmaf(p, f, 2.4022651e-1f);
    p = fmaf(p, f, 6.9314718e-1f);
    p = fmaf(p, f, 1.0f);
    int e = (int)n;
    float sc = __int_as_float((e + 127) << 23);
    return p * sc;
}
__device__ __forceinline__ float frcp(float s) {
    float x = __int_as_float(0x7EF311C3u - __float_as_int(s));
    x = x * fmaf(-s, x, 2.0f);
    x = x * fmaf(-s, x, 2.0f);
    x = x * fmaf(-s, x, 2.0f);
    return x;
}
__device__ __forceinline__ void softmax3(float& a, float& b, float& c) {
    const float L2E = 1.4426950408889634f;
    float m  = fmaxf(a, fmaxf(b, c));
    float mL = m * L2E;
    float e0 = fexp2(fmaf(a, L2E, -mL));
    float e1 = fexp2(fmaf(b, L2E, -mL));
    float e2 = fexp2(fmaf(c, L2E, -mL));
    float r  = frcp(e0 + e1 + e2);
    a = e0 * r; b = e1 * r; c = e2 * r;
}

// ==================== mma.sync attention ====================
// Per CTA: (b, h, 128-q tile). s-loop over 16 tiles of 64.
// SMEM (bytes): QH 0 (16K), QL 16384,
//   KH[a]=32768+a*16384, KL=KH+8192   (rows s=64, panels 2x4096)
//   VH[a]=81920+a*16384, VL=VH+8192   (rows d=64, cols s, panels 2x4096)
//   PH[a]=131072+a*32768, PL=PH+16384 (rows q=128, cols s, panels 2x8192)
// Total 229376 B.
#define ATT_SMEM 229376

__global__ void __launch_bounds__(256, 1)
attn_mma()
{
    extern __shared__ char sm[];
    const uint32_t sb = smem_u32(sm);
    const int tid = threadIdx.x, lane = tid & 31, w = tid >> 5;
    const int wm = w >> 2, wn = w & 3;
    const int b = blockIdx.z, h = blockIdx.y, q0 = blockIdx.x * 128;

    const float* Qg = g_Q  + ((size_t)(b * NHz + h)) * Sz * HDz;
    const float* Kg = g_K  + ((size_t)(b * NHz + h)) * Az * Sz * HDz;
    const float* Vg = g_Vt + ((size_t)(b * NHz + h)) * Az * HDz * Sz;

    // ---- load Q (resident, split) ----
#pragma unroll
    for (int i = 0; i < 8; i++) {
        int idx = tid + i * 256;
        int row = idx >> 4, c = idx & 15;
        float4 v = *(const float4*)(Qg + (size_t)(q0 + row) * 64 + c * 4);
        uint2 hi, lo; cvt_split(v, hi, lo);
        uint32_t off = (uint32_t)(c >> 3) * 8192u + SWZ64((uint32_t)row * 64u + (c & 7) * 8u);
        *(uint2*)(sm + off)         = hi;
        *(uint2*)(sm + 16384 + off) = lo;
    }

    float o[4][2][4];
#pragma unroll
    for (int mi = 0; mi < 4; mi++)
#pragma unroll
        for (int ni = 0; ni < 2; ni++)
#pragma unroll
            for (int e = 0; e < 4; e++) o[mi][ni][e] = 0.0f;

    const int arow = lane & 15;
    const int akb  = (lane >> 4) << 4;
    const int brow = (lane & 7) + ((lane & 16) >> 1);
    const int bkb  = (lane & 8) << 1;
    const int g = lane >> 2, t = lane & 3;

    for (int s0 = 0; s0 < Sz; s0 += 64) {
        __syncthreads();   // previous PV done; K/V/P reusable

        // ---- load K (3 adapters, split) ----
#pragma unroll
        for (int i = 0; i < 12; i++) {
            int idx = tid + i * 256;
            int a = idx >> 10, rem = idx & 1023;
            int row = rem >> 4, c = rem & 15;
            float4 v = *(const float4*)(Kg + (size_t)a * Sz * 64 + (size_t)(s0 + row) * 64 + c * 4);
            uint2 hi, lo; cvt_split(v, hi, lo);
            uint32_t off = (uint32_t)(c >> 3) * 4096u + SWZ64((uint32_t)row * 64u + (c & 7) * 8u);
            *(uint2*)(sm + 32768 + a * 16384 + off)        = hi;
            *(uint2*)(sm + 32768 + a * 16384 + 8192 + off) = lo;
        }
        // ---- load V (transposed layout [d][s], split) ----
#pragma unroll
        for (int i = 0; i < 12; i++) {
            int idx = tid + i * 256;
            int a = idx >> 10, rem = idx & 1023;
            int row = rem >> 4, c = rem & 15;   // row = d, cols = s
            float4 v = *(const float4*)(Vg + (size_t)a * HDz * Sz + (size_t)row * Sz + s0 + c * 4);
            uint2 hi, lo; cvt_split(v, hi, lo);
            uint32_t off = (uint32_t)(c >> 3) * 4096u + SWZ64((uint32_t)row * 64u + (c & 7) * 8u);
            *(uint2*)(sm + 81920 + a * 16384 + off)        = hi;
            *(uint2*)(sm + 81920 + a * 16384 + 8192 + off) = lo;
        }
        __syncthreads();

        // ---- scores: S_a = Q . K_a^T  (3-pass bf16 split), warp tile 64q x 16s ----
        float acc[3][4][2][4];
#pragma unroll
        for (int a = 0; a < 3; a++)
#pragma unroll
            for (int mi = 0; mi < 4; mi++)
#pragma unroll
                for (int ni = 0; ni < 2; ni++)
#pragma unroll
                    for (int e = 0; e < 4; e++) acc[a][mi][ni][e] = 0.0f;

#pragma unroll
        for (int kk = 0; kk < 4; kk++) {
            const uint32_t qpan = (uint32_t)(kk >> 1) * 8192u;
            const uint32_t kpan = (uint32_t)(kk >> 1) * 4096u;
            const uint32_t kof  = (uint32_t)(kk & 1) * 32u;
            uint32_t fah[4][4], fal[4][4];
#pragma unroll
            for (int mi = 0; mi < 4; mi++) {
                uint32_t off = SWZ64((uint32_t)(wm * 64 + mi * 16 + arow) * 64u + kof + akb);
                ldsm_x4(fah[mi], sb + qpan + off);
                ldsm_x4(fal[mi], sb + 16384 + qpan + off);
            }
#pragma unroll
            for (int a = 0; a < 3; a++) {
                uint32_t kb = sb + 32768u + (uint32_t)a * 16384u + kpan;
                uint32_t off = SWZ64((uint32_t)(wn * 16 + brow) * 64u + kof + bkb);
                uint32_t fbh[4], fbl[4];
                ldsm_x4(fbh, kb + off);
                ldsm_x4(fbl, kb + 8192 + off);
#pragma unroll
                for (int mi = 0; mi < 4; mi++)
#pragma unroll
                    for (int ni = 0; ni < 2; ni++) {
                        mma16816(acc[a][mi][ni], fah[mi], &fbh[ni * 2]);
                        mma16816(acc[a][mi][ni], fah[mi], &fbl[ni * 2]);
                        mma16816(acc[a][mi][ni], fal[mi], &fbh[ni * 2]);
                    }
            }
        }

        // ---- softmax over adapter axis (registers) ----
#pragma unroll
        for (int mi = 0; mi < 4; mi++)
#pragma unroll
            for (int ni = 0; ni < 2; ni++)
#pragma unroll
                for (int e = 0; e < 4; e++)
                    softmax3(acc[0][mi][ni][e], acc[1][mi][ni][e], acc[2][mi][ni][e]);

        // ---- store P to SMEM (bf16 split) ----
#pragma unroll
        for (int a = 0; a < 3; a++)
#pragma unroll
            for (int mi = 0; mi < 4; mi++)
#pragma unroll
                for (int ni = 0; ni < 2; ni++) {
                    int q = wm * 64 + mi * 16 + g;
                    int s = wn * 16 + ni * 8 + 2 * t;
                    uint32_t p = (uint32_t)(s >> 5) * 8192u;
                    uint32_t sc = (uint32_t)(s & 31) * 2u;
                    uint32_t hi, lo;
                    split2(acc[a][mi][ni][0], acc[a][mi][ni][1], hi, lo);
                    uint32_t off = p + SWZ64((uint32_t)q * 64u + sc);
                    *(uint32_t*)(sm + 131072 + a * 32768 + off)         = hi;
                    *(uint32_t*)(sm + 131072 + a * 32768 + 16384 + off) = lo;
                    split2(acc[a][mi][ni][2], acc[a][mi][ni][3], hi, lo);
                    off = p + SWZ64((uint32_t)(q + 8) * 64u + sc);
                    *(uint32_t*)(sm + 131072 + a * 32768 + off)         = hi;
                    *(uint32_t*)(sm + 131072 + a * 32768 + 16384 + off) = lo;
                }
        __syncthreads();

        // ---- PV: o += P_a . V_a  (k = s), warp tile 64q x 16d ----
#pragma unroll
        for (int a = 0; a < 3; a++) {
            const uint32_t pb = sb + 131072u + (uint32_t)a * 32768u;
            const uint32_t vb = sb + 81920u  + (uint32_t)a * 16384u;
#pragma unroll
            for (int kk = 0; kk < 4; kk++) {
                const uint32_t ppan = (uint32_t)(kk >> 1) * 8192u;
                const uint32_t vpan = (uint32_t)(kk >> 1) * 4096u;
                const uint32_t kof  = (uint32_t)(kk & 1) * 32u;
                uint32_t fah[4][4], fal[4][4];
#pragma unroll
                for (int mi = 0; mi < 4; mi++) {
                    uint32_t off = SWZ64((uint32_t)(wm * 64 + mi * 16 + arow) * 64u + kof + akb);
                    ldsm_x4(fah[mi], pb + ppan + off);
                    ldsm_x4(fal[mi], pb + 16384 + ppan + off);
                }
                uint32_t off = SWZ64((uint32_t)(wn * 16 + brow) * 64u + kof + bkb);
                uint32_t fbh[4], fbl[4];
                ldsm_x4(fbh, vb + vpan + off);
                ldsm_x4(fbl, vb + 8192 + vpan + off);
#pragma unroll
                for (int mi = 0; mi < 4; mi++)
#pragma unroll
                    for (int ni = 0; ni < 2; ni++) {
                        mma16816(o[mi][ni], fah[mi], &fbh[ni * 2]);
                        mma16816(o[mi][ni], fah[mi], &fbl[ni * 2]);
                        mma16816(o[mi][ni], fal[mi], &fbh[ni * 2]);
                    }
            }
        }
    }

    // ---- epilogue: attended -> g_att [B,S,H] ----
#pragma unroll
    for (int mi = 0; mi < 4; mi++)
#pragma unroll
        for (int ni = 0; ni < 2; ni++) {
            const int col = h * 64 + wn * 16 + ni * 8 + 2 * t;
            const int q = q0 + wm * 64 + mi * 16 + g;
            *(float2*)(g_att + ((size_t)b * Sz + q) * Hz + col)
                = make_float2(o[mi][ni][0], o[mi][ni][1]);
            *(float2*)(g_att + ((size_t)b * Sz + q + 8) * Hz + col)
                = make_float2(o[mi][ni][2], o[mi][ni][3]);
        }
}

// -------------------- LayerNorm over H=768 per row --------------------
__global__ void __launch_bounds__(256)
ln_kernel(const float* __restrict__ gamma, const float* __restrict__ beta,
          float* __restrict__ out)
{
    const int row = blockIdx.x;
    const int tid = threadIdx.x;
    const float* x = g_res + (size_t)row * Hz;

    float v0 = x[tid], v1 = x[tid + 256], v2 = x[tid + 512];
    float s  = v0 + v1 + v2;
    float ss = v0 * v0 + v1 * v1 + v2 * v2;

    __shared__ float rs[8], rss[8];
#pragma unroll
    for (int o = 16; o; o >>= 1) {
        s  += __shfl_xor_sync(0xffffffffu, s,  o);
        ss += __shfl_xor_sync(0xffffffffu, ss, o);
    }
    if ((tid & 31) == 0) { rs[tid >> 5] = s; rss[tid >> 5] = ss; }
    __syncthreads();
    if (tid == 0) {
        float S = 0.f, SS = 0.f;
#pragma unroll
        for (int i = 0; i < 8; i++) { S += rs[i]; SS += rss[i]; }
        rs[0] = S; rss[0] = SS;
    }
    __syncthreads();
    float mu  = rs[0]  * (1.0f / 768.0f);
    float var = rss[0] * (1.0f / 768.0f) - mu * mu;
    float inv = rsqrtf(var + 1e-5f);

    float* o = out + (size_t)row * Hz;
    o[tid]       = (v0 - mu) * inv * gamma[tid]       + beta[tid];
    o[tid + 256] = (v1 - mu) * inv * gamma[tid + 256] + beta[tid + 256];
    o[tid + 512] = (v2 - mu) * inv * gamma[tid + 512] + beta[tid + 512];
}

// -------------------- avg_weights == 1/3 analytically --------------------
__global__ void __launch_bounds__(256)
fill_third(float* __restrict__ p)
{
    size_t i = (size_t)blockIdx.x * 256 + threadIdx.x;
    const float t = 1.0f / 3.0f;
    ((float4*)p)[i] = make_float4(t, t, t, t);
}

// -------------------- launch --------------------
extern "C" void kernel_launch(void* const* d_in, const int* in_sizes, int n_in,
                              void* d_out, int out_size)
{
    const float* query = (const float*)d_in[0];
    const float* adap  = (const float*)d_in[1];
    const float* Wq    = (const float*)d_in[2];
    const float* bq    = (const float*)d_in[3];
    const float* Wk    = (const float*)d_in[4];
    const float* bk    = (const float*)d_in[5];
    const float* Wv    = (const float*)d_in[6];
    const float* bv    = (const float*)d_in[7];
    const float* Wo    = (const float*)d_in[8];
    const float* bo    = (const float*)d_in[9];
    const float* gamma = (const float*)d_in[10];
    const float* beta  = (const float*)d_in[11];

    float* out = (float*)d_out;
    float* avg = out + (size_t)Bz * Sz * Hz;

    cudaFuncSetAttribute(attn_mma,    cudaFuncAttributeMaxDynamicSharedMemorySize, ATT_SMEM);
    cudaFuncSetAttribute(gemm_mma<0>, cudaFuncAttributeMaxDynamicSharedMemorySize, GMM_SMEM);
    cudaFuncSetAttribute(gemm_mma<1>, cudaFuncAttributeMaxDynamicSharedMemorySize, GMM_SMEM);
    cudaFuncSetAttribute(gemm_mma<2>, cudaFuncAttributeMaxDynamicSharedMemorySize, GMM_SMEM);
    cudaFuncSetAttribute(gemm_mma<3>, cudaFuncAttributeMaxDynamicSharedMemorySize, GMM_SMEM);

    dim3 blk(256);

    // avg_weights = 1/3
    fill_third<<<(Bz * Sz * Sz) / 4 / 256, blk>>>(avg);

    // projections (mma.sync bf16, 2-term split)
    gemm_mma<0><<<dim3((Bz * Sz) / 128, Hz / 128),      blk, GMM_SMEM>>>(query, Wq, bq, nullptr);
    gemm_mma<1><<<dim3((Bz * Az * Sz) / 128, Hz / 128), blk, GMM_SMEM>>>(adap,  Wk, bk, nullptr);
    gemm_mma<2><<<dim3((Bz * Az * Sz) / 128, Hz / 128), blk, GMM_SMEM>>>(adap,  Wv, bv, nullptr);

    // attention (mma.sync bf16, 2-term split)
    attn_mma<<<dim3(Sz / 128, NHz, Bz), blk, ATT_SMEM>>>();

    // output projection + residual, then LayerNorm
    gemm_mma<3><<<dim3((Bz * Sz) / 128, Hz / 128), blk, GMM_SMEM>>>(nullptr, Wo, bo, query);
    ln_kernel<<<Bz * Sz, blk>>>(gamma, beta, out);
}

// round 6
// speedup vs baseline: 3.0616x; 1.2221x over previous
#include <cuda_runtime.h>
#include <cuda_bf16.h>
#include <cstdint>

// Problem constants
#define Bz   4
#define Az   3
#define Sz   1024
#define Hz   768
#define NHz  12
#define HDz  64

typedef unsigned long long u64;

// -------------------- scratch (device globals; no allocation) --------------------
// pre-split bf16 inputs
__device__ __nv_bfloat16 g_qh [Bz*Sz*Hz],        g_ql [Bz*Sz*Hz];          // query
__device__ __nv_bfloat16 g_xh [Bz*Az*Sz*Hz],     g_xl [Bz*Az*Sz*Hz];       // adapter
__device__ __nv_bfloat16 g_wqh[Hz*Hz], g_wql[Hz*Hz];
__device__ __nv_bfloat16 g_wkh[Hz*Hz], g_wkl[Hz*Hz];
__device__ __nv_bfloat16 g_wvh[Hz*Hz], g_wvl[Hz*Hz];
__device__ __nv_bfloat16 g_woh[Hz*Hz], g_wol[Hz*Hz];
// projected tensors (split)
__device__ __nv_bfloat16 g_Qh [Bz*NHz*Sz*HDz],    g_Ql [Bz*NHz*Sz*HDz];    // [b][h][s][d] (x 1/8)
__device__ __nv_bfloat16 g_Kh [Bz*NHz*Az*Sz*HDz], g_Kl [Bz*NHz*Az*Sz*HDz]; // [b][h][a][s][d]
__device__ __nv_bfloat16 g_Vth[Bz*NHz*Az*HDz*Sz], g_Vtl[Bz*NHz*Az*HDz*Sz]; // [b][h][a][d][s]
__device__ __nv_bfloat16 g_atth[Bz*Sz*Hz],        g_attl[Bz*Sz*Hz];        // attended (split)
__device__ float g_res[Bz*Sz*Hz];                                          // pre-LN fp32

// SW64 swizzle for 64-byte SMEM rows
#define SWZ64(o) ((o) ^ (((o) >> 3) & 0x30))

__device__ __forceinline__ uint32_t smem_u32(const void* p) {
    uint32_t a;
    asm("{ .reg .u64 t; cvta.to.shared.u64 t, %1; cvt.u32.u64 %0, t; }"
        : "=r"(a) : "l"(p));
    return a;
}
__device__ __forceinline__ void ldsm_x4(uint32_t* f, uint32_t a) {
    asm volatile("ldmatrix.sync.aligned.m8n8.x4.shared.b16 {%0,%1,%2,%3}, [%4];"
                 : "=r"(f[0]), "=r"(f[1]), "=r"(f[2]), "=r"(f[3]) : "r"(a));
}
__device__ __forceinline__ void mma16816(float* d, const uint32_t* a, const uint32_t* b) {
    asm volatile("mma.sync.aligned.m16n8k16.row.col.f32.bf16.bf16.f32 "
                 "{%0,%1,%2,%3}, {%4,%5,%6,%7}, {%8,%9}, {%0,%1,%2,%3};"
                 : "+f"(d[0]), "+f"(d[1]), "+f"(d[2]), "+f"(d[3])
                 : "r"(a[0]), "r"(a[1]), "r"(a[2]), "r"(a[3]), "r"(b[0]), "r"(b[1]));
}
__device__ __forceinline__ void cpa16(uint32_t dst, const void* src) {
    asm volatile("cp.async.cg.shared.global [%0], [%1], 16;" :: "r"(dst), "l"(src));
}
#define CP_COMMIT() asm volatile("cp.async.commit_group;" ::: "memory")
#define CP_WAIT(n)  asm volatile("cp.async.wait_group %0;" :: "n"(n) : "memory")

// fp32 float4 -> (bf16 hi x4, bf16 lo x4) packed as 2x uint2
__device__ __forceinline__ void cvt_split(float4 v, uint2& hi, uint2& lo) {
    uint32_t h0, h1;
    asm("cvt.rn.bf16x2.f32 %0, %1, %2;" : "=r"(h0) : "f"(v.y), "f"(v.x));
    asm("cvt.rn.bf16x2.f32 %0, %1, %2;" : "=r"(h1) : "f"(v.w), "f"(v.z));
    float hx = __uint_as_float(h0 << 16);
    float hy = __uint_as_float(h0 & 0xffff0000u);
    float hz = __uint_as_float(h1 << 16);
    float hw = __uint_as_float(h1 & 0xffff0000u);
    uint32_t l0, l1;
    asm("cvt.rn.bf16x2.f32 %0, %1, %2;" : "=r"(l0) : "f"(v.y - hy), "f"(v.x - hx));
    asm("cvt.rn.bf16x2.f32 %0, %1, %2;" : "=r"(l1) : "f"(v.w - hw), "f"(v.z - hz));
    hi = make_uint2(h0, h1);
    lo = make_uint2(l0, l1);
}
// fp32 pair -> bf16x2 hi + bf16x2 lo (x in low half, y in high half)
__device__ __forceinline__ void split2(float x, float y, uint32_t& hi, uint32_t& lo) {
    asm("cvt.rn.bf16x2.f32 %0, %1, %2;" : "=r"(hi) : "f"(y), "f"(x));
    float hx = __uint_as_float(hi << 16);
    float hy = __uint_as_float(hi & 0xffff0000u);
    asm("cvt.rn.bf16x2.f32 %0, %1, %2;" : "=r"(lo) : "f"(y - hy), "f"(x - hx));
}

// -------------------- prep: split fp32 -> bf16 hi/lo --------------------
template <int ID>
__global__ void __launch_bounds__(256)
split_f32(const float* __restrict__ src)
{
    size_t i = (size_t)blockIdx.x * 256 + threadIdx.x;
    float4 v = ((const float4*)src)[i];
    uint2 hi, lo; cvt_split(v, hi, lo);
    __nv_bfloat16 *dh, *dl;
    if      (ID == 0) { dh = g_qh;  dl = g_ql;  }
    else if (ID == 1) { dh = g_xh;  dl = g_xl;  }
    else if (ID == 2) { dh = g_wqh; dl = g_wql; }
    else if (ID == 3) { dh = g_wkh; dl = g_wkl; }
    else if (ID == 4) { dh = g_wvh; dl = g_wvl; }
    else              { dh = g_woh; dl = g_wol; }
    ((uint2*)dh)[i] = hi;
    ((uint2*)dl)[i] = lo;
}

// ==================== mma.sync projection GEMM, cp.async 3-stage ====================
// out[m][n] = sum_k A[m][k] * W[n][k]  (A, W pre-split bf16)
// MODE 0: -> g_Qh/l (x0.125, head layout)   MODE 1: -> g_Kh/l
// MODE 2: -> g_Vth/l (transposed)           MODE 3: -> g_res (+bias+resid, fp32)
#define GMM_SMEM (3 * 32768)

template <int MODE>
__global__ void __launch_bounds__(256)
gemm_bf16(const float* __restrict__ bias, const float* __restrict__ resid)
{
    extern __shared__ char sm[];
    const uint32_t sb = smem_u32(sm);
    const int tid = threadIdx.x, lane = tid & 31, w = tid >> 5;
    const int wm = w >> 2, wn = w & 3;
    const int m0 = blockIdx.x * 128, n0 = blockIdx.y * 128;

    const __nv_bfloat16 *Ah, *Al, *Bh, *Bl;
    if      (MODE == 0) { Ah = g_qh;   Al = g_ql;   Bh = g_wqh; Bl = g_wql; }
    else if (MODE == 1) { Ah = g_xh;   Al = g_xl;   Bh = g_wkh; Bl = g_wkl; }
    else if (MODE == 2) { Ah = g_xh;   Al = g_xl;   Bh = g_wvh; Bl = g_wvl; }
    else                { Ah = g_atth; Al = g_attl; Bh = g_woh; Bl = g_wol; }

    auto issue_stage = [&](int kt, int buf) {
        const uint32_t SB = sb + (uint32_t)buf * 32768u;
#pragma unroll
        for (int i = 0; i < 2; i++) {
            int j = tid + i * 256;            // 0..511
            int row = j >> 2, c = j & 3;      // 128 rows x 4 x 16B
            uint32_t dst = SB + SWZ64((uint32_t)row * 64u + (uint32_t)c * 16u);
            size_t aoff = (size_t)(m0 + row) * Hz + kt * 32 + c * 8;
            size_t boff = (size_t)(n0 + row) * Hz + kt * 32 + c * 8;
            cpa16(dst,          Ah + aoff);
            cpa16(dst + 8192u,  Al + aoff);
            cpa16(dst + 16384u, Bh + boff);
            cpa16(dst + 24576u, Bl + boff);
        }
    };

    issue_stage(0, 0); CP_COMMIT();
    issue_stage(1, 1); CP_COMMIT();

    float acc[4][4][4];
#pragma unroll
    for (int a = 0; a < 4; a++)
#pragma unroll
        for (int b = 0; b < 4; b++)
#pragma unroll
            for (int c = 0; c < 4; c++) acc[a][b][c] = 0.0f;

    const int arow = lane & 15;
    const int akb  = (lane >> 4) << 4;
    const int brow = (lane & 7) + ((lane & 16) >> 1);
    const int bkb  = (lane & 8) << 1;

    for (int s = 0; s < 24; s++) {
        if (s + 2 < 24) issue_stage(s + 2, (s + 2) % 3);
        CP_COMMIT();
        if (s >= 22) { CP_WAIT(0); } else { CP_WAIT(2); }
        __syncthreads();

        const uint32_t base = sb + (uint32_t)(s % 3) * 32768u;
#pragma unroll
        for (int k16 = 0; k16 < 2; k16++) {
            const int kof = k16 * 32;
            uint32_t fa[4][4], fbh[2][4], fbl[2][4];
#pragma unroll
            for (int mi = 0; mi < 4; mi++) {
                uint32_t off = (uint32_t)((wm * 64 + mi * 16 + arow) * 64 + kof + akb);
                ldsm_x4(fa[mi], base + SWZ64(off));
            }
#pragma unroll
            for (int ni = 0; ni < 2; ni++) {
                uint32_t off = (uint32_t)((wn * 32 + ni * 16 + brow) * 64 + kof + bkb);
                ldsm_x4(fbh[ni], base + 16384u + SWZ64(off));
                ldsm_x4(fbl[ni], base + 24576u + SWZ64(off));
            }
#pragma unroll
            for (int mi = 0; mi < 4; mi++)
#pragma unroll
                for (int ni = 0; ni < 4; ni++) {
                    mma16816(acc[mi][ni], fa[mi], &fbh[ni >> 1][(ni & 1) * 2]);
                    mma16816(acc[mi][ni], fa[mi], &fbl[ni >> 1][(ni & 1) * 2]);
                }
#pragma unroll
            for (int mi = 0; mi < 4; mi++) {
                uint32_t off = (uint32_t)((wm * 64 + mi * 16 + arow) * 64 + kof + akb);
                ldsm_x4(fa[mi], base + 8192u + SWZ64(off));
            }
#pragma unroll
            for (int mi = 0; mi < 4; mi++)
#pragma unroll
                for (int ni = 0; ni < 4; ni++)
                    mma16816(acc[mi][ni], fa[mi], &fbh[ni >> 1][(ni & 1) * 2]);
        }
        __syncthreads();
    }

    // ---- epilogue ----
    const int g = lane >> 2, t = lane & 3;
#pragma unroll
    for (int ni = 0; ni < 4; ni++) {
        const int col = n0 + wn * 32 + ni * 8 + 2 * t;
        const float2 bs = *(const float2*)(bias + col);
#pragma unroll
        for (int mi = 0; mi < 4; mi++) {
            const int r0 = m0 + wm * 64 + mi * 16 + g;
#pragma unroll
            for (int half = 0; half < 2; half++) {
                const int row = r0 + half * 8;
                float vx = acc[mi][ni][half * 2 + 0] + bs.x;
                float vy = acc[mi][ni][half * 2 + 1] + bs.y;
                if (MODE == 0) {
                    const int b = row >> 10, ss = row & 1023;
                    const int h = col >> 6, d = col & 63;
                    uint32_t hi, lo; split2(vx * 0.125f, vy * 0.125f, hi, lo);
                    size_t off = (((size_t)(b * NHz + h)) * Sz + ss) * HDz + d;
                    *(uint32_t*)(g_Qh + off) = hi;
                    *(uint32_t*)(g_Ql + off) = lo;
                } else if (MODE == 1) {
                    const int b = row / (Az * Sz), rr = row - b * (Az * Sz);
                    const int a = rr >> 10, ss = rr & 1023;
                    const int h = col >> 6, d = col & 63;
                    uint32_t hi, lo; split2(vx, vy, hi, lo);
                    size_t off = ((((size_t)(b * NHz + h)) * Az + a) * Sz + ss) * HDz + d;
                    *(uint32_t*)(g_Kh + off) = hi;
                    *(uint32_t*)(g_Kl + off) = lo;
                } else if (MODE == 2) {
                    const int b = row / (Az * Sz), rr = row - b * (Az * Sz);
                    const int a = rr >> 10, ss = rr & 1023;
                    const int h = col >> 6, d = col & 63;
                    uint32_t hi, lo; split2(vx, vy, hi, lo);
                    size_t off = ((((size_t)(b * NHz + h)) * Az + a) * HDz + d) * Sz + ss;
                    uint16_t* ph = (uint16_t*)(g_Vth + off);
                    uint16_t* pl = (uint16_t*)(g_Vtl + off);
                    ph[0]  = (uint16_t)hi;  ph[Sz] = (uint16_t)(hi >> 16);
                    pl[0]  = (uint16_t)lo;  pl[Sz] = (uint16_t)(lo >> 16);
                } else {
                    const float2 q = *(const float2*)(resid + (size_t)row * Hz + col);
                    *(float2*)(g_res + (size_t)row * Hz + col)
                        = make_float2(vx + q.x, vy + q.y);
                }
            }
        }
    }
}

// -------------------- fast exp2 / rcp --------------------
__device__ __forceinline__ float fexp2(float x) {
    x = fmaxf(x, -120.0f);
    float n = floorf(x);
    float f = x - n;
    float p =             1.5404e-4f;
    p = fmaf(p, f, 1.3333558e-3f);
    p = fmaf(p, f, 9.6181291e-3f);
    p = fmaf(p, f, 5.5504109e-2f);
    p = fmaf(p, f, 2.4022651e-1f);
    p = fmaf(p, f, 6.9314718e-1f);
    p = fmaf(p, f, 1.0f);
    int e = (int)n;
    float sc = __int_as_float((e + 127) << 23);
    return p * sc;
}
__device__ __forceinline__ float frcp(float s) {
    float x = __int_as_float(0x7EF311C3u - __float_as_int(s));
    x = x * fmaf(-s, x, 2.0f);
    x = x * fmaf(-s, x, 2.0f);
    x = x * fmaf(-s, x, 2.0f);
    return x;
}
__device__ __forceinline__ void softmax3(float& a, float& b, float& c) {
    const float L2E = 1.4426950408889634f;
    float m  = fmaxf(a, fmaxf(b, c));
    float mL = m * L2E;
    float e0 = fexp2(fmaf(a, L2E, -mL));
    float e1 = fexp2(fmaf(b, L2E, -mL));
    float e2 = fexp2(fmaf(c, L2E, -mL));
    float r  = frcp(e0 + e1 + e2);
    a = e0 * r; b = e1 * r; c = e2 * r;
}

// ==================== attention: P-in-registers, cp.async double buffer ====================
// Per CTA: (b, h, 128-q tile); warp w owns q rows [w*16, w*16+16).
// SMEM: Q split [0, 32768); K/V stage buffers 2 x 98304 at 32768 / 131072.
// Pipeline: 2 buffers -> prefetch distance 1 (stage ti+1 issued at iteration ti,
// AFTER the end-of-iteration barrier of ti-1 guaranteed all reads of that buffer done).
#define ATT_SMEM 229376

__global__ void __launch_bounds__(256, 1)
attn_mma()
{
    extern __shared__ char sm[];
    const uint32_t sb = smem_u32(sm);
    const int tid = threadIdx.x, lane = tid & 31, w = tid >> 5;
    const int b = blockIdx.z, h = blockIdx.y, q0 = blockIdx.x * 128;
    const size_t bh = (size_t)(b * NHz + h);

    const __nv_bfloat16* Qh = g_Qh  + bh * Sz * HDz;
    const __nv_bfloat16* Ql = g_Ql  + bh * Sz * HDz;
    const __nv_bfloat16* Kh = g_Kh  + bh * Az * Sz * HDz;
    const __nv_bfloat16* Kl = g_Kl  + bh * Az * Sz * HDz;
    const __nv_bfloat16* Vh = g_Vth + bh * Az * HDz * Sz;
    const __nv_bfloat16* Vl = g_Vtl + bh * Az * HDz * Sz;

    auto issue_kv = [&](int s0, uint32_t SB) {
#pragma unroll
        for (int i = 0; i < 12; i++) {
            int j = tid + i * 256;            // 0..3071
            int comp = j >> 9;                // 0..5
            int a = comp >> 1, hl = comp & 1;
            int cj = j & 511;
            int row = cj >> 3, c = cj & 7;
            uint32_t dst = SB + (uint32_t)a * 16384u + (uint32_t)hl * 8192u
                         + (uint32_t)(c >> 2) * 4096u
                         + SWZ64((uint32_t)row * 64u + (uint32_t)(c & 3) * 16u);
            const __nv_bfloat16* ks = (hl ? Kl : Kh) + (size_t)a * Sz * HDz
                                     + (size_t)(s0 + row) * HDz + c * 8;
            cpa16(dst, ks);
            const __nv_bfloat16* vs = (hl ? Vl : Vh) + (size_t)a * HDz * Sz
                                     + (size_t)row * Sz + s0 + c * 8;
            cpa16(dst + 49152u, vs);
        }
    };

    // prologue: Q + K/V stage 0 (one group)
#pragma unroll
    for (int i = 0; i < 4; i++) {
        int j = tid + i * 256;                // 0..1023
        int row = j >> 3, c = j & 7;
        uint32_t dst = (uint32_t)(c >> 2) * 8192u
                     + SWZ64((uint32_t)row * 64u + (uint32_t)(c & 3) * 16u);
        cpa16(sb + dst,          Qh + (size_t)(q0 + row) * HDz + c * 8);
        cpa16(sb + 16384u + dst, Ql + (size_t)(q0 + row) * HDz + c * 8);
    }
    issue_kv(0, sb + 32768u);
    CP_COMMIT();

    float o[8][4];
#pragma unroll
    for (int n8 = 0; n8 < 8; n8++)
#pragma unroll
        for (int e = 0; e < 4; e++) o[n8][e] = 0.0f;

    const int arow = lane & 15;
    const int akb  = (lane >> 4) << 4;
    const int brow = (lane & 7) + ((lane & 16) >> 1);
    const int bkb  = (lane & 8) << 1;
    const int g = lane >> 2, t = lane & 3;

    for (int ti = 0; ti < 16; ti++) {
        // prefetch distance 1: stage ti+1 into the buffer last read at ti-1
        if (ti + 1 < 16) issue_kv((ti + 1) * 64, sb + 32768u + (uint32_t)((ti + 1) & 1) * 98304u);
        CP_COMMIT();
        if (ti + 1 < 16) { CP_WAIT(1); } else { CP_WAIT(0); }
        __syncthreads();

        const uint32_t KB = sb + 32768u + (uint32_t)(ti & 1) * 98304u;
        const uint32_t VB = KB + 49152u;

        // ---- scores: acc[a][n8 over 64 s][4], 3-pass split ----
        float acc[3][8][4];
#pragma unroll
        for (int a = 0; a < 3; a++)
#pragma unroll
            for (int n8 = 0; n8 < 8; n8++)
#pragma unroll
                for (int e = 0; e < 4; e++) acc[a][n8][e] = 0.0f;

#pragma unroll
        for (int kk = 0; kk < 4; kk++) {
            uint32_t aoff = (uint32_t)(kk >> 1) * 8192u
                          + SWZ64((uint32_t)(w * 16 + arow) * 64u + (uint32_t)(kk & 1) * 32u + akb);
            uint32_t fah[4], fal[4];
            ldsm_x4(fah, sb + aoff);
            ldsm_x4(fal, sb + 16384u + aoff);
#pragma unroll
            for (int a = 0; a < 3; a++) {
                uint32_t kbase = KB + (uint32_t)a * 16384u + (uint32_t)(kk >> 1) * 4096u;
#pragma unroll
                for (int sg = 0; sg < 4; sg++) {
                    uint32_t boff = SWZ64((uint32_t)(sg * 16 + brow) * 64u
                                          + (uint32_t)(kk & 1) * 32u + bkb);
                    uint32_t fbh[4], fbl[4];
                    ldsm_x4(fbh, kbase + boff);
                    ldsm_x4(fbl, kbase + 8192u + boff);
#pragma unroll
                    for (int nn = 0; nn < 2; nn++) {
                        mma16816(acc[a][sg * 2 + nn], fah, &fbh[nn * 2]);
                        mma16816(acc[a][sg * 2 + nn], fah, &fbl[nn * 2]);
                        mma16816(acc[a][sg * 2 + nn], fal, &fbh[nn * 2]);
                    }
                }
            }
        }

        // ---- softmax over adapter axis (registers) ----
#pragma unroll
        for (int n8 = 0; n8 < 8; n8++)
#pragma unroll
            for (int e = 0; e < 4; e++)
                softmax3(acc[0][n8][e], acc[1][n8][e], acc[2][n8][e]);

        // ---- PV: c-frag -> a-frag in registers, per adapter ----
#pragma unroll
        for (int a = 0; a < 3; a++) {
            uint32_t ph[4][4], pl[4][4];
#pragma unroll
            for (int kc = 0; kc < 4; kc++) {
                split2(acc[a][kc*2][0],   acc[a][kc*2][1],   ph[kc][0], pl[kc][0]);
                split2(acc[a][kc*2][2],   acc[a][kc*2][3],   ph[kc][1], pl[kc][1]);
                split2(acc[a][kc*2+1][0], acc[a][kc*2+1][1], ph[kc][2], pl[kc][2]);
                split2(acc[a][kc*2+1][2], acc[a][kc*2+1][3], ph[kc][3], pl[kc][3]);
            }
            uint32_t vbA = VB + (uint32_t)a * 16384u;
#pragma unroll
            for (int kc = 0; kc < 4; kc++) {
                uint32_t vbase = vbA + (uint32_t)(kc >> 1) * 4096u;
#pragma unroll
                for (int dg = 0; dg < 4; dg++) {
                    uint32_t boff = SWZ64((uint32_t)(dg * 16 + brow) * 64u
                                          + (uint32_t)(kc & 1) * 32u + bkb);
                    uint32_t fbh[4], fbl[4];
                    ldsm_x4(fbh, vbase + boff);
                    ldsm_x4(fbl, vbase + 8192u + boff);
#pragma unroll
                    for (int nn = 0; nn < 2; nn++) {
                        mma16816(o[dg * 2 + nn], ph[kc], &fbh[nn * 2]);
                        mma16816(o[dg * 2 + nn], ph[kc], &fbl[nn * 2]);
                        mma16816(o[dg * 2 + nn], pl[kc], &fbh[nn * 2]);
                    }
                }
            }
        }
        __syncthreads();   // all reads of buffer (ti&1) done before it is refilled
    }

    // ---- epilogue: write split attended for gemm<3> ----
    const int q = q0 + w * 16 + g;
#pragma unroll
    for (int n8 = 0; n8 < 8; n8++) {
        const int col = h * 64 + n8 * 8 + 2 * t;
        uint32_t hi, lo;
        split2(o[n8][0], o[n8][1], hi, lo);
        size_t off0 = ((size_t)b * Sz + q) * Hz + col;
        *(uint32_t*)(g_atth + off0) = hi;
        *(uint32_t*)(g_attl + off0) = lo;
        split2(o[n8][2], o[n8][3], hi, lo);
        size_t off1 = ((size_t)b * Sz + q + 8) * Hz + col;
        *(uint32_t*)(g_atth + off1) = hi;
        *(uint32_t*)(g_attl + off1) = lo;
    }
}

// -------------------- LayerNorm over H=768 per row --------------------
__global__ void __launch_bounds__(256)
ln_kernel(const float* __restrict__ gamma, const float* __restrict__ beta,
          float* __restrict__ out)
{
    const int row = blockIdx.x;
    const int tid = threadIdx.x;
    const float* x = g_res + (size_t)row * Hz;

    float v0 = x[tid], v1 = x[tid + 256], v2 = x[tid + 512];
    float s  = v0 + v1 + v2;
    float ss = v0 * v0 + v1 * v1 + v2 * v2;

    __shared__ float rs[8], rss[8];
#pragma unroll
    for (int o = 16; o; o >>= 1) {
        s  += __shfl_xor_sync(0xffffffffu, s,  o);
        ss += __shfl_xor_sync(0xffffffffu, ss, o);
    }
    if ((tid & 31) == 0) { rs[tid >> 5] = s; rss[tid >> 5] = ss; }
    __syncthreads();
    if (tid == 0) {
        float S = 0.f, SS = 0.f;
#pragma unroll
        for (int i = 0; i < 8; i++) { S += rs[i]; SS += rss[i]; }
        rs[0] = S; rss[0] = SS;
    }
    __syncthreads();
    float mu  = rs[0]  * (1.0f / 768.0f);
    float var = rss[0] * (1.0f / 768.0f) - mu * mu;
    float inv = rsqrtf(var + 1e-5f);

    float* o = out + (size_t)row * Hz;
    o[tid]       = (v0 - mu) * inv * gamma[tid]       + beta[tid];
    o[tid + 256] = (v1 - mu) * inv * gamma[tid + 256] + beta[tid + 256];
    o[tid + 512] = (v2 - mu) * inv * gamma[tid + 512] + beta[tid + 512];
}

// -------------------- avg_weights == 1/3 analytically --------------------
__global__ void __launch_bounds__(256)
fill_third(float* __restrict__ p)
{
    size_t i = (size_t)blockIdx.x * 256 + threadIdx.x;
    const float t = 1.0f / 3.0f;
    ((float4*)p)[i] = make_float4(t, t, t, t);
}

// -------------------- launch --------------------
extern "C" void kernel_launch(void* const* d_in, const int* in_sizes, int n_in,
                              void* d_out, int out_size)
{
    const float* query = (const float*)d_in[0];
    const float* adap  = (const float*)d_in[1];
    const float* Wq    = (const float*)d_in[2];
    const float* bq    = (const float*)d_in[3];
    const float* Wk    = (const float*)d_in[4];
    const float* bk    = (const float*)d_in[5];
    const float* Wv    = (const float*)d_in[6];
    const float* bv    = (const float*)d_in[7];
    const float* Wo    = (const float*)d_in[8];
    const float* bo    = (const float*)d_in[9];
    const float* gamma = (const float*)d_in[10];
    const float* beta  = (const float*)d_in[11];

    float* out = (float*)d_out;
    float* avg = out + (size_t)Bz * Sz * Hz;

    cudaFuncSetAttribute(attn_mma,     cudaFuncAttributeMaxDynamicSharedMemorySize, ATT_SMEM);
    cudaFuncSetAttribute(gemm_bf16<0>, cudaFuncAttributeMaxDynamicSharedMemorySize, GMM_SMEM);
    cudaFuncSetAttribute(gemm_bf16<1>, cudaFuncAttributeMaxDynamicSharedMemorySize, GMM_SMEM);
    cudaFuncSetAttribute(gemm_bf16<2>, cudaFuncAttributeMaxDynamicSharedMemorySize, GMM_SMEM);
    cudaFuncSetAttribute(gemm_bf16<3>, cudaFuncAttributeMaxDynamicSharedMemorySize, GMM_SMEM);

    dim3 blk(256);

    // avg_weights = 1/3
    fill_third<<<(Bz * Sz * Sz) / 4 / 256, blk>>>(avg);

    // pre-split inputs
    split_f32<0><<<(Bz * Sz * Hz) / 1024, blk>>>(query);
    split_f32<1><<<(Bz * Az * Sz * Hz) / 1024, blk>>>(adap);
    split_f32<2><<<(Hz * Hz) / 1024, blk>>>(Wq);
    split_f32<3><<<(Hz * Hz) / 1024, blk>>>(Wk);
    split_f32<4><<<(Hz * Hz) / 1024, blk>>>(Wv);
    split_f32<5><<<(Hz * Hz) / 1024, blk>>>(Wo);

    // projections
    gemm_bf16<0><<<dim3((Bz * Sz) / 128, Hz / 128),      blk, GMM_SMEM>>>(bq, nullptr);
    gemm_bf16<1><<<dim3((Bz * Az * Sz) / 128, Hz / 128), blk, GMM_SMEM>>>(bk, nullptr);
    gemm_bf16<2><<<dim3((Bz * Az * Sz) / 128, Hz / 128), blk, GMM_SMEM>>>(bv, nullptr);

    // attention
    attn_mma<<<dim3(Sz / 128, NHz, Bz), blk, ATT_SMEM>>>();

    // output projection + residual, then LayerNorm
    gemm_bf16<3><<<dim3((Bz * Sz) / 128, Hz / 128), blk, GMM_SMEM>>>(bo, query);
    ln_kernel<<<Bz * Sz, blk>>>(gamma, beta, out);
}